// round 9
// baseline (speedup 1.0000x reference)
#include <cuda_runtime.h>
#include <cuda_bf16.h>
#include <cstdint>

#define BN    4096
#define NV    2
#define DD    128
#define NN    8192
#define NCLS  100
#define TILE  128
#define NT    (NN/TILE)            // 64
#define NTILES (NT*(NT+1)/2)       // 2080
#define INV_T 14.285714285714286f
#define EXPC  20.60992915555662f   // INV_T * log2(e)
#define LN2   0.6931471805599453f
#define GSMEM (65536)              // gemm kernel: A(32K)+B(32K)
#define MAXN  192                  // max 2*class_count supported
#define SPLIT 8                    // p-stripes per class
#define CSMEM (MAXN * 65 * 4)      // bf16 rows padded to 260B = 65 u32

// ---------------- device scratch ----------------
__device__ __align__(16) float          g_Q [(size_t)NN * DD];
__device__ __align__(16) __nv_bfloat16  g_Qh[(size_t)NN * DD];
__device__ float g_allsum[NN];      // sum_{j != i} exp(l_ij), unmasked
__device__ float g_possum[NN];      // sum over same-label non-self exp(l)
__device__ float g_loss;
__device__ int   g_offset[NCLS + 1];
__device__ int   g_list[BN];
__device__ float g_Lmat[(size_t)NCLS * MAXN * MAXN];   // per-class raw dot matrices

// ---------------- helpers ----------------
__device__ __forceinline__ uint32_t smem_u32(const void* p) {
    uint32_t a;
    asm("{ .reg .u64 t; cvta.to.shared.u64 t, %1; cvt.u32.u64 %0, t; }" : "=r"(a) : "l"(p));
    return a;
}
__device__ __forceinline__ void ldsm_x4(uint32_t* r, uint32_t addr) {
    asm volatile("ldmatrix.sync.aligned.m8n8.x4.shared.b16 {%0,%1,%2,%3}, [%4];"
                 : "=r"(r[0]), "=r"(r[1]), "=r"(r[2]), "=r"(r[3]) : "r"(addr));
}
__device__ __forceinline__ void mma16816(float* c, const uint32_t* a, uint32_t b0, uint32_t b1) {
    asm volatile(
        "mma.sync.aligned.m16n8k16.row.col.f32.bf16.bf16.f32 "
        "{%0,%1,%2,%3}, {%4,%5,%6,%7}, {%8,%9}, {%0,%1,%2,%3};"
        : "+f"(c[0]), "+f"(c[1]), "+f"(c[2]), "+f"(c[3])
        : "r"(a[0]), "r"(a[1]), "r"(a[2]), "r"(a[3]), "r"(b0), "r"(b1));
}
__device__ __forceinline__ float ex2f(float x) {
    float y; asm("ex2.approx.f32 %0, %1;" : "=f"(y) : "f"(x)); return y;
}
__device__ __forceinline__ float lg2f(float x) {
    float y; asm("lg2.approx.f32 %0, %1;" : "=f"(y) : "f"(x)); return y;
}
__device__ __forceinline__ float exp_m(float dot) { return ex2f(dot * EXPC); }
__device__ __forceinline__ float2 bf2f(uint32_t u) {
    float2 r;
    r.x = __uint_as_float(u << 16);
    r.y = __uint_as_float(u & 0xFFFF0000u);
    return r;
}

// ---------------- 1: normalize (blocks 0..1023) + fused setup (block 1024) ----------------
__global__ void normalize_setup_kernel(const float* __restrict__ feat,
                                       const int* __restrict__ lab) {
    if (blockIdx.x == 1024) {
        // class lists + zero allsum (256 threads)
        __shared__ int scount[NCLS], soff[NCLS + 1], scur[NCLS];
        int tid = threadIdx.x;
        if (tid < NCLS) { scount[tid] = 0; scur[tid] = 0; }
        __syncthreads();
        for (int t = tid; t < BN; t += 256) atomicAdd(&scount[lab[t]], 1);
        __syncthreads();
        if (tid == 0) {
            int a = 0;
            for (int c = 0; c < NCLS; c++) { soff[c] = a; a += scount[c]; }
            soff[NCLS] = a;
            g_loss = 0.f;
        }
        __syncthreads();
        for (int t = tid; t < BN; t += 256) {
            int c = lab[t];
            g_list[soff[c] + atomicAdd(&scur[c], 1)] = t;
        }
        if (tid <= NCLS) g_offset[tid] = soff[tid];
        for (int t = tid; t < NN; t += 256) g_allsum[t] = 0.f;
        return;
    }
    int warp = threadIdx.x >> 5, lane = threadIdx.x & 31;
    int row = blockIdx.x * 8 + warp;
    int v = row >> 12, b = row & (BN - 1);
    float4 x = ((const float4*)(feat + (size_t)(b * NV + v) * DD))[lane];
    float ss = x.x * x.x + x.y * x.y + x.z * x.z + x.w * x.w;
#pragma unroll
    for (int o = 16; o; o >>= 1) ss += __shfl_xor_sync(0xffffffffu, ss, o);
    float inv = rsqrtf(ss);
    float4 y = make_float4(x.x * inv, x.y * inv, x.z * inv, x.w * inv);
    ((float4*)(g_Q + (size_t)row * DD))[lane] = y;
    uint32_t h01 = (uint32_t)__bfloat16_as_ushort(__float2bfloat16(y.x)) |
                   ((uint32_t)__bfloat16_as_ushort(__float2bfloat16(y.y)) << 16);
    uint32_t h23 = (uint32_t)__bfloat16_as_ushort(__float2bfloat16(y.z)) |
                   ((uint32_t)__bfloat16_as_ushort(__float2bfloat16(y.w)) << 16);
    ((uint2*)(g_Qh + (size_t)row * DD))[lane] = make_uint2(h01, h23);
}

// ---------------- 2: persistent mma.sync GEMM + exp row/col sums ----------------
__global__ void __launch_bounds__(256, 2) gemm_rowsum_kernel() {
    extern __shared__ __align__(16) char smem[];
    uint32_t sA = smem_u32(smem);
    uint32_t sB = sA + 32768u;

    int tid = threadIdx.x;
    int w = tid >> 5, ln = tid & 31;
    int wm = w >> 2, wn = w & 3;

    int a_r = wm * 64 + (ln & 15);
    int b_r = wn * 32 + (ln & 7) + ((ln >> 4) << 3);
    int a_cs = (ln >> 4);
    int b_cs = ((ln >> 3) & 1);
    int ln7 = ln & 7;
    int r0 = ln >> 2;
    int c0 = (ln & 3) * 2;

    for (int t = blockIdx.x; t < NTILES; t += gridDim.x) {
        int ti = 0, tt = t;
        while (tt >= NT - ti) { tt -= NT - ti; ti++; }
        int tj = ti + tt;
        bool diag = (ti == tj);
        int rowbase = ti * TILE, colbase = tj * TILE;

#pragma unroll
        for (int i = 0; i < 8; i++) {
            int idx = tid + i * 256;
            int r = idx >> 4, cc = idx & 15;
            uint4 va = *((const uint4*)(g_Qh + (size_t)(rowbase + r) * DD) + cc);
            uint4 vb = *((const uint4*)(g_Qh + (size_t)(colbase + r) * DD) + cc);
            uint32_t off = (uint32_t)(r * 256 + ((cc ^ (r & 7)) << 4));
            *(uint4*)(smem + off) = va;
            *(uint4*)(smem + 32768 + off) = vb;
        }
        __syncthreads();

        float acc[4][4][4];
#pragma unroll
        for (int mt = 0; mt < 4; mt++)
#pragma unroll
            for (int nj = 0; nj < 4; nj++)
#pragma unroll
                for (int q = 0; q < 4; q++) acc[mt][nj][q] = 0.f;

#pragma unroll
        for (int ks = 0; ks < 8; ks++) {
            uint32_t a[4][4], b[2][4];
#pragma unroll
            for (int mt = 0; mt < 4; mt++) {
                int r = a_r + mt * 16;
                ldsm_x4(a[mt], sA + (uint32_t)(r * 256 + (((ks * 2 + a_cs) ^ ln7) << 4)));
            }
#pragma unroll
            for (int ng = 0; ng < 2; ng++) {
                int r = b_r + ng * 16;
                ldsm_x4(b[ng], sB + (uint32_t)(r * 256 + (((ks * 2 + b_cs) ^ ln7) << 4)));
            }
#pragma unroll
            for (int mt = 0; mt < 4; mt++)
#pragma unroll
                for (int nj = 0; nj < 4; nj++)
                    mma16816(acc[mt][nj], a[mt], b[nj >> 1][(nj & 1) * 2], b[nj >> 1][(nj & 1) * 2 + 1]);
        }

        float rs[4][2], cs[4][2];
#pragma unroll
        for (int q = 0; q < 4; q++) { rs[q][0] = rs[q][1] = 0.f; cs[q][0] = cs[q][1] = 0.f; }
#pragma unroll
        for (int mt = 0; mt < 4; mt++) {
            int rg0 = wm * 64 + mt * 16 + r0, rg1 = rg0 + 8;
#pragma unroll
            for (int nj = 0; nj < 4; nj++) {
                int cg0 = wn * 32 + nj * 8 + c0;
                float e0 = exp_m(acc[mt][nj][0]);
                float e1 = exp_m(acc[mt][nj][1]);
                float e2 = exp_m(acc[mt][nj][2]);
                float e3 = exp_m(acc[mt][nj][3]);
                if (diag) {
                    if (rg0 == cg0)     e0 = 0.f;
                    if (rg0 == cg0 + 1) e1 = 0.f;
                    if (rg1 == cg0)     e2 = 0.f;
                    if (rg1 == cg0 + 1) e3 = 0.f;
                }
                rs[mt][0] += e0 + e1;  rs[mt][1] += e2 + e3;
                cs[nj][0] += e0 + e2;  cs[nj][1] += e1 + e3;
            }
        }
#pragma unroll
        for (int mt = 0; mt < 4; mt++)
#pragma unroll
            for (int h = 0; h < 2; h++) {
                float v = rs[mt][h];
                v += __shfl_xor_sync(0xffffffffu, v, 1);
                v += __shfl_xor_sync(0xffffffffu, v, 2);
                rs[mt][h] = v;
            }
        if ((ln & 3) == 0) {
#pragma unroll
            for (int mt = 0; mt < 4; mt++)
#pragma unroll
                for (int h = 0; h < 2; h++)
                    atomicAdd(&g_allsum[rowbase + wm * 64 + mt * 16 + r0 + h * 8], rs[mt][h]);
        }
        if (!diag) {
#pragma unroll
            for (int nj = 0; nj < 4; nj++)
#pragma unroll
                for (int p = 0; p < 2; p++) {
                    float v = cs[nj][p];
                    v += __shfl_xor_sync(0xffffffffu, v, 4);
                    v += __shfl_xor_sync(0xffffffffu, v, 8);
                    v += __shfl_xor_sync(0xffffffffu, v, 16);
                    cs[nj][p] = v;
                }
            if (ln < 4) {
#pragma unroll
                for (int nj = 0; nj < 4; nj++)
#pragma unroll
                    for (int p = 0; p < 2; p++)
                        atomicAdd(&g_allsum[colbase + wn * 32 + nj * 8 + c0 + p], cs[nj][p]);
            }
        }
        __syncthreads();
    }
}

// ---------------- 3: per-class Gram stripes -> Lmat + possum ----------------
// grid = NCLS*SPLIT; block (c,stripe) handles p = stripe + SPLIT*(w + 8*i).
__global__ void __launch_bounds__(256, 2) pos_gram_kernel() {
    extern __shared__ __align__(16) uint32_t Cs[];   // [MAXN][65]
    __shared__ int jmap[MAXN];
    int c = blockIdx.x >> 3, stripe = blockIdx.x & 7;
    int start = g_offset[c];
    int n = 2 * (g_offset[c + 1] - start);
    if (n > MAXN) n = MAXN;
    int tid = threadIdx.x, w = tid >> 5, ln = tid & 31;
    float* Lc = g_Lmat + (size_t)c * MAXN * MAXN;

    for (int idx = tid; idx < n * 32; idx += 256) {
        int r = idx >> 5, kk = idx & 31;
        int j = ((r & 1) << 12) + g_list[start + (r >> 1)];
        uint2 v = ((const uint2*)g_Qh)[(size_t)j * 32 + kk];
        Cs[r * 65 + kk * 2] = v.x;
        Cs[r * 65 + kk * 2 + 1] = v.y;
        if (kk == 0) jmap[r] = j;
    }
    __syncthreads();

    for (int k = w;; k += 8) {
        int p = stripe + SPLIT * k;
        if (p >= n) break;
        const uint32_t* Cp = Cs + p * 65;
        float* Lp = Lc + p * MAXN;
        float rsum = 0.f;
        for (int qb = 0; qb < n; qb += 32) {
            int q = qb + ln;
            bool qok = (q < n);
            const uint32_t* Cq = Cs + (qok ? q : 0) * 65;
            float a0 = 0.f, a1 = 0.f, a2 = 0.f, a3 = 0.f;
#pragma unroll 4
            for (int kp = 0; kp < 64; kp += 4) {
                float2 q0 = bf2f(Cq[kp]),     p0 = bf2f(Cp[kp]);
                float2 q1 = bf2f(Cq[kp + 1]), p1 = bf2f(Cp[kp + 1]);
                float2 q2 = bf2f(Cq[kp + 2]), p2 = bf2f(Cp[kp + 2]);
                float2 q3 = bf2f(Cq[kp + 3]), p3 = bf2f(Cp[kp + 3]);
                a0 = fmaf(p0.x, q0.x, a0); a0 = fmaf(p0.y, q0.y, a0);
                a1 = fmaf(p1.x, q1.x, a1); a1 = fmaf(p1.y, q1.y, a1);
                a2 = fmaf(p2.x, q2.x, a2); a2 = fmaf(p2.y, q2.y, a2);
                a3 = fmaf(p3.x, q3.x, a3); a3 = fmaf(p3.y, q3.y, a3);
            }
            float acc = (a0 + a1) + (a2 + a3);
            if (qok) {
                Lp[q] = acc;
                if (q != p) rsum += exp_m(acc);
            }
        }
#pragma unroll
        for (int o = 16; o; o >>= 1) rsum += __shfl_xor_sync(0xffffffffu, rsum, o);
        if (ln == 0) g_possum[jmap[p]] = rsum;
    }
}

// ---------------- 4: loss from Lmat + negsum ----------------
__global__ void __launch_bounds__(256) pos_loss_kernel() {
    __shared__ float ns[MAXN];
    __shared__ float wl[8];
    int c = blockIdx.x >> 3, stripe = blockIdx.x & 7;
    int start = g_offset[c];
    int n = 2 * (g_offset[c + 1] - start);
    if (n > MAXN) n = MAXN;
    int tid = threadIdx.x, w = tid >> 5, ln = tid & 31;
    const float* Lc = g_Lmat + (size_t)c * MAXN * MAXN;

    for (int r = tid; r < n; r += 256) {
        int j = ((r & 1) << 12) + g_list[start + (r >> 1)];
        ns[r] = g_allsum[j] - g_possum[j];
    }
    __syncthreads();

    float part = 0.f;
    for (int k = w;; k += 8) {
        int p = stripe + SPLIT * k;
        if (p >= n) break;
        const float* Lp = Lc + p * MAXN;
        for (int qb = 0; qb < n; qb += 32) {
            int q = qb + ln;
            if (q < n && q != p) {
                float dot = Lp[q];
                float e = exp_m(dot);
                part += dot * INV_T - LN2 * lg2f(ns[q] + e);
            }
        }
    }
#pragma unroll
    for (int o = 16; o; o >>= 1) part += __shfl_xor_sync(0xffffffffu, part, o);
    if (ln == 0) wl[w] = part;
    __syncthreads();
    if (tid == 0) {
        float s = 0.f;
#pragma unroll
        for (int i = 0; i < 8; i++) s += wl[i];
        atomicAdd(&g_loss, s);
    }
}

// ---------------- 5: finalize ----------------
__global__ void finalize_kernel(float* __restrict__ out) {
    out[0] = -g_loss * (1.0f / (float)NN);
}

// ---------------- launch ----------------
extern "C" void kernel_launch(void* const* d_in, const int* in_sizes, int n_in,
                              void* d_out, int out_size) {
    const float* feat = (const float*)d_in[0];
    const int* lab = (const int*)d_in[1];
    float* out = (float*)d_out;

    static int smem_set = 0;
    if (!smem_set) {
        cudaFuncSetAttribute(gemm_rowsum_kernel,
                             cudaFuncAttributeMaxDynamicSharedMemorySize, GSMEM);
        cudaFuncSetAttribute(pos_gram_kernel,
                             cudaFuncAttributeMaxDynamicSharedMemorySize, CSMEM);
        smem_set = 1;
    }

    normalize_setup_kernel<<<1025, 256>>>(feat, lab);
    gemm_rowsum_kernel<<<296, 256, GSMEM>>>();
    pos_gram_kernel<<<NCLS * SPLIT, 256, CSMEM>>>();
    pos_loss_kernel<<<NCLS * SPLIT, 256>>>();
    finalize_kernel<<<1, 1>>>(out);
}

// round 10
// speedup vs baseline: 1.0222x; 1.0222x over previous
#include <cuda_runtime.h>
#include <cuda_bf16.h>
#include <cstdint>

#define BN    4096
#define NV    2
#define DD    128
#define NN    8192
#define NCLS  100
#define TILE  128
#define NT    (NN/TILE)            // 64
#define INV_T 14.285714285714286f
#define EXPC  20.60992915555662f   // INV_T * log2(e)
#define LN2   0.6931471805599453f
#define CHUNK 7                    // B tiles per block (same ti row-band)
#define GGRID 325                  // sum_ti ceil((64-ti)/7)
#define GSMEM (98304)              // A(32K) + B0(32K) + B1(32K)
#define MAXN  192
#define SPLIT 8
#define CSMEM (MAXN * 65 * 4)

// ---------------- device scratch ----------------
__device__ __align__(16) __nv_bfloat16  g_Qh[(size_t)NN * DD];
__device__ float g_allsum[NN];
__device__ float g_possum[NN];
__device__ float g_loss;
__device__ int   g_offset[NCLS + 1];
__device__ int   g_list[BN];
__device__ float g_Lmat[(size_t)NCLS * MAXN * MAXN];

// ---------------- helpers ----------------
__device__ __forceinline__ uint32_t smem_u32(const void* p) {
    uint32_t a;
    asm("{ .reg .u64 t; cvta.to.shared.u64 t, %1; cvt.u32.u64 %0, t; }" : "=r"(a) : "l"(p));
    return a;
}
__device__ __forceinline__ void ldsm_x4(uint32_t* r, uint32_t addr) {
    asm volatile("ldmatrix.sync.aligned.m8n8.x4.shared.b16 {%0,%1,%2,%3}, [%4];"
                 : "=r"(r[0]), "=r"(r[1]), "=r"(r[2]), "=r"(r[3]) : "r"(addr));
}
__device__ __forceinline__ void mma16816(float* c, const uint32_t* a, uint32_t b0, uint32_t b1) {
    asm volatile(
        "mma.sync.aligned.m16n8k16.row.col.f32.bf16.bf16.f32 "
        "{%0,%1,%2,%3}, {%4,%5,%6,%7}, {%8,%9}, {%0,%1,%2,%3};"
        : "+f"(c[0]), "+f"(c[1]), "+f"(c[2]), "+f"(c[3])
        : "r"(a[0]), "r"(a[1]), "r"(a[2]), "r"(a[3]), "r"(b0), "r"(b1));
}
__device__ __forceinline__ float ex2f(float x) {
    float y; asm("ex2.approx.f32 %0, %1;" : "=f"(y) : "f"(x)); return y;
}
__device__ __forceinline__ float lg2f(float x) {
    float y; asm("lg2.approx.f32 %0, %1;" : "=f"(y) : "f"(x)); return y;
}
__device__ __forceinline__ float exp_m(float dot) { return ex2f(dot * EXPC); }
__device__ __forceinline__ float2 bf2f(uint32_t u) {
    float2 r;
    r.x = __uint_as_float(u << 16);
    r.y = __uint_as_float(u & 0xFFFF0000u);
    return r;
}
// async 16B copy global->shared + B-tile loader
__device__ __forceinline__ void cp16(uint32_t saddr, const void* g) {
    asm volatile("cp.async.cg.shared.global [%0], [%1], 16;" :: "r"(saddr), "l"(g));
}
__device__ __forceinline__ void cp_b_tile(uint32_t sbase, int colbase, int tid) {
#pragma unroll
    for (int i = 0; i < 8; i++) {
        int idx = tid + i * 256;
        int r = idx >> 4, cc = idx & 15;
        const uint4* g = ((const uint4*)(g_Qh + (size_t)(colbase + r) * DD)) + cc;
        cp16(sbase + (uint32_t)(r * 256 + ((cc ^ (r & 7)) << 4)), g);
    }
    asm volatile("cp.async.commit_group;" ::: "memory");
}

// ---------------- 1: normalize (blocks 0..1023) + fused setup (block 1024) ----------------
__global__ void normalize_setup_kernel(const float* __restrict__ feat,
                                       const int* __restrict__ lab) {
    if (blockIdx.x == 1024) {
        __shared__ int scount[NCLS], soff[NCLS + 1], scur[NCLS];
        int tid = threadIdx.x;
        if (tid < NCLS) { scount[tid] = 0; scur[tid] = 0; }
        __syncthreads();
        for (int t = tid; t < BN; t += 256) atomicAdd(&scount[lab[t]], 1);
        __syncthreads();
        if (tid == 0) {
            int a = 0;
            for (int c = 0; c < NCLS; c++) { soff[c] = a; a += scount[c]; }
            soff[NCLS] = a;
            g_loss = 0.f;
        }
        __syncthreads();
        for (int t = tid; t < BN; t += 256) {
            int c = lab[t];
            g_list[soff[c] + atomicAdd(&scur[c], 1)] = t;
        }
        if (tid <= NCLS) g_offset[tid] = soff[tid];
        for (int t = tid; t < NN; t += 256) g_allsum[t] = 0.f;
        return;
    }
    int warp = threadIdx.x >> 5, lane = threadIdx.x & 31;
    int row = blockIdx.x * 8 + warp;
    int v = row >> 12, b = row & (BN - 1);
    float4 x = ((const float4*)(feat + (size_t)(b * NV + v) * DD))[lane];
    float ss = x.x * x.x + x.y * x.y + x.z * x.z + x.w * x.w;
#pragma unroll
    for (int o = 16; o; o >>= 1) ss += __shfl_xor_sync(0xffffffffu, ss, o);
    float inv = rsqrtf(ss);
    uint32_t h01 = (uint32_t)__bfloat16_as_ushort(__float2bfloat16(x.x * inv)) |
                   ((uint32_t)__bfloat16_as_ushort(__float2bfloat16(x.y * inv)) << 16);
    uint32_t h23 = (uint32_t)__bfloat16_as_ushort(__float2bfloat16(x.z * inv)) |
                   ((uint32_t)__bfloat16_as_ushort(__float2bfloat16(x.w * inv)) << 16);
    ((uint2*)(g_Qh + (size_t)row * DD))[lane] = make_uint2(h01, h23);
}

// ---------------- 2: row-band GEMM, A-resident, cp.async double-buffered B ----------------
__global__ void __launch_bounds__(256, 2) gemm_rowsum_kernel() {
    extern __shared__ __align__(16) char smem[];
    uint32_t sA = smem_u32(smem);

    // decode block -> (ti row, tj chunk)
    int bid = blockIdx.x, ti = 0;
    for (;;) {
        int nb = (NT - ti + CHUNK - 1) / CHUNK;
        if (bid < nb) break;
        bid -= nb; ti++;
    }
    int tj0 = ti + bid * CHUNK;
    int tjend = ti + (bid + 1) * CHUNK; if (tjend > NT) tjend = NT;
    int rowbase = ti * TILE;

    int tid = threadIdx.x;
    int w = tid >> 5, ln = tid & 31;
    int wm = w >> 2, wn = w & 3;

    int a_r = wm * 64 + (ln & 15);
    int b_r = wn * 32 + (ln & 7) + ((ln >> 4) << 3);
    int a_cs = (ln >> 4);
    int b_cs = ((ln >> 3) & 1);
    int ln7 = ln & 7;
    int r0 = ln >> 2;
    int c0 = (ln & 3) * 2;

    // A tile: load once for the whole chunk
#pragma unroll
    for (int i = 0; i < 8; i++) {
        int idx = tid + i * 256;
        int r = idx >> 4, cc = idx & 15;
        uint4 va = *((const uint4*)(g_Qh + (size_t)(rowbase + r) * DD) + cc);
        *(uint4*)(smem + r * 256 + ((cc ^ (r & 7)) << 4)) = va;
    }
    // prefetch first B tile
    cp_b_tile(sA + 32768u, tj0 * TILE, tid);

    float rsacc[4][2];   // row-sum partials, accumulated across the whole chunk
#pragma unroll
    for (int q = 0; q < 4; q++) { rsacc[q][0] = 0.f; rsacc[q][1] = 0.f; }

    for (int tj = tj0, it = 0; tj < tjend; tj++, it++) {
        uint32_t sB = sA + 32768u + ((uint32_t)(it & 1) << 15);
        bool diag = (ti == tj);
        int colbase = tj * TILE;

        if (tj + 1 < tjend) {
            cp_b_tile(sA + 32768u + ((uint32_t)((it + 1) & 1) << 15), (tj + 1) * TILE, tid);
            asm volatile("cp.async.wait_group 1;" ::: "memory");
        } else {
            asm volatile("cp.async.wait_group 0;" ::: "memory");
        }
        __syncthreads();   // B(buf) visible to all; A visible (first iter)

        float acc[4][4][4];
#pragma unroll
        for (int mt = 0; mt < 4; mt++)
#pragma unroll
            for (int nj = 0; nj < 4; nj++)
#pragma unroll
                for (int q = 0; q < 4; q++) acc[mt][nj][q] = 0.f;

#pragma unroll
        for (int ks = 0; ks < 8; ks++) {
            uint32_t a[4][4], b[2][4];
#pragma unroll
            for (int mt = 0; mt < 4; mt++) {
                int r = a_r + mt * 16;
                ldsm_x4(a[mt], sA + (uint32_t)(r * 256 + (((ks * 2 + a_cs) ^ ln7) << 4)));
            }
#pragma unroll
            for (int ng = 0; ng < 2; ng++) {
                int r = b_r + ng * 16;
                ldsm_x4(b[ng], sB + (uint32_t)(r * 256 + (((ks * 2 + b_cs) ^ ln7) << 4)));
            }
#pragma unroll
            for (int mt = 0; mt < 4; mt++)
#pragma unroll
                for (int nj = 0; nj < 4; nj++)
                    mma16816(acc[mt][nj], a[mt], b[nj >> 1][(nj & 1) * 2], b[nj >> 1][(nj & 1) * 2 + 1]);
        }

        float cs[4][2];
#pragma unroll
        for (int q = 0; q < 4; q++) { cs[q][0] = 0.f; cs[q][1] = 0.f; }
#pragma unroll
        for (int mt = 0; mt < 4; mt++) {
            int rg0 = wm * 64 + mt * 16 + r0, rg1 = rg0 + 8;
#pragma unroll
            for (int nj = 0; nj < 4; nj++) {
                int cg0 = wn * 32 + nj * 8 + c0;
                float e0 = exp_m(acc[mt][nj][0]);
                float e1 = exp_m(acc[mt][nj][1]);
                float e2 = exp_m(acc[mt][nj][2]);
                float e3 = exp_m(acc[mt][nj][3]);
                if (diag) {
                    if (rg0 == cg0)     e0 = 0.f;
                    if (rg0 == cg0 + 1) e1 = 0.f;
                    if (rg1 == cg0)     e2 = 0.f;
                    if (rg1 == cg0 + 1) e3 = 0.f;
                }
                rsacc[mt][0] += e0 + e1;  rsacc[mt][1] += e2 + e3;
                cs[nj][0] += e0 + e2;     cs[nj][1] += e1 + e3;
            }
        }
        if (!diag) {
#pragma unroll
            for (int nj = 0; nj < 4; nj++)
#pragma unroll
                for (int p = 0; p < 2; p++) {
                    float v = cs[nj][p];
                    v += __shfl_xor_sync(0xffffffffu, v, 4);
                    v += __shfl_xor_sync(0xffffffffu, v, 8);
                    v += __shfl_xor_sync(0xffffffffu, v, 16);
                    cs[nj][p] = v;
                }
            if (ln < 4) {
#pragma unroll
                for (int nj = 0; nj < 4; nj++)
#pragma unroll
                    for (int p = 0; p < 2; p++)
                        atomicAdd(&g_allsum[colbase + wn * 32 + nj * 8 + c0 + p], cs[nj][p]);
            }
        }
        __syncthreads();   // all reads of sB(buf) done before it is re-prefetched
    }

    // one row-sum atomic per row for the whole chunk
#pragma unroll
    for (int mt = 0; mt < 4; mt++)
#pragma unroll
        for (int h = 0; h < 2; h++) {
            float v = rsacc[mt][h];
            v += __shfl_xor_sync(0xffffffffu, v, 1);
            v += __shfl_xor_sync(0xffffffffu, v, 2);
            rsacc[mt][h] = v;
        }
    if ((ln & 3) == 0) {
#pragma unroll
        for (int mt = 0; mt < 4; mt++)
#pragma unroll
            for (int h = 0; h < 2; h++)
                atomicAdd(&g_allsum[rowbase + wm * 64 + mt * 16 + r0 + h * 8], rsacc[mt][h]);
    }
}

// ---------------- 3: per-class Gram stripes -> Lmat + possum ----------------
__global__ void __launch_bounds__(256, 2) pos_gram_kernel() {
    extern __shared__ __align__(16) uint32_t Cs[];   // [MAXN][65]
    __shared__ int jmap[MAXN];
    int c = blockIdx.x >> 3, stripe = blockIdx.x & 7;
    int start = g_offset[c];
    int n = 2 * (g_offset[c + 1] - start);
    if (n > MAXN) n = MAXN;
    int tid = threadIdx.x, w = tid >> 5, ln = tid & 31;
    float* Lc = g_Lmat + (size_t)c * MAXN * MAXN;

    for (int idx = tid; idx < n * 32; idx += 256) {
        int r = idx >> 5, kk = idx & 31;
        int j = ((r & 1) << 12) + g_list[start + (r >> 1)];
        uint2 v = ((const uint2*)g_Qh)[(size_t)j * 32 + kk];
        Cs[r * 65 + kk * 2] = v.x;
        Cs[r * 65 + kk * 2 + 1] = v.y;
        if (kk == 0) jmap[r] = j;
    }
    __syncthreads();

    for (int k = w;; k += 8) {
        int p = stripe + SPLIT * k;
        if (p >= n) break;
        const uint32_t* Cp = Cs + p * 65;
        float* Lp = Lc + p * MAXN;
        float rsum = 0.f;
        for (int qb = 0; qb < n; qb += 32) {
            int q = qb + ln;
            bool qok = (q < n);
            const uint32_t* Cq = Cs + (qok ? q : 0) * 65;
            float a0 = 0.f, a1 = 0.f, a2 = 0.f, a3 = 0.f;
#pragma unroll 4
            for (int kp = 0; kp < 64; kp += 4) {
                float2 q0 = bf2f(Cq[kp]),     p0 = bf2f(Cp[kp]);
                float2 q1 = bf2f(Cq[kp + 1]), p1 = bf2f(Cp[kp + 1]);
                float2 q2 = bf2f(Cq[kp + 2]), p2 = bf2f(Cp[kp + 2]);
                float2 q3 = bf2f(Cq[kp + 3]), p3 = bf2f(Cp[kp + 3]);
                a0 = fmaf(p0.x, q0.x, a0); a0 = fmaf(p0.y, q0.y, a0);
                a1 = fmaf(p1.x, q1.x, a1); a1 = fmaf(p1.y, q1.y, a1);
                a2 = fmaf(p2.x, q2.x, a2); a2 = fmaf(p2.y, q2.y, a2);
                a3 = fmaf(p3.x, q3.x, a3); a3 = fmaf(p3.y, q3.y, a3);
            }
            float acc = (a0 + a1) + (a2 + a3);
            if (qok) {
                Lp[q] = acc;
                if (q != p) rsum += exp_m(acc);
            }
        }
#pragma unroll
        for (int o = 16; o; o >>= 1) rsum += __shfl_xor_sync(0xffffffffu, rsum, o);
        if (ln == 0) g_possum[jmap[p]] = rsum;
    }
}

// ---------------- 4: loss from Lmat + negsum ----------------
__global__ void __launch_bounds__(256) pos_loss_kernel() {
    __shared__ float ns[MAXN];
    __shared__ float wl[8];
    int c = blockIdx.x >> 3, stripe = blockIdx.x & 7;
    int start = g_offset[c];
    int n = 2 * (g_offset[c + 1] - start);
    if (n > MAXN) n = MAXN;
    int tid = threadIdx.x, w = tid >> 5, ln = tid & 31;
    const float* Lc = g_Lmat + (size_t)c * MAXN * MAXN;

    for (int r = tid; r < n; r += 256) {
        int j = ((r & 1) << 12) + g_list[start + (r >> 1)];
        ns[r] = g_allsum[j] - g_possum[j];
    }
    __syncthreads();

    float part = 0.f;
    for (int k = w;; k += 8) {
        int p = stripe + SPLIT * k;
        if (p >= n) break;
        const float* Lp = Lc + p * MAXN;
        for (int qb = 0; qb < n; qb += 32) {
            int q = qb + ln;
            if (q < n && q != p) {
                float dot = Lp[q];
                float e = exp_m(dot);
                part += dot * INV_T - LN2 * lg2f(ns[q] + e);
            }
        }
    }
#pragma unroll
    for (int o = 16; o; o >>= 1) part += __shfl_xor_sync(0xffffffffu, part, o);
    if (ln == 0) wl[w] = part;
    __syncthreads();
    if (tid == 0) {
        float s = 0.f;
#pragma unroll
        for (int i = 0; i < 8; i++) s += wl[i];
        atomicAdd(&g_loss, s);
    }
}

// ---------------- 5: finalize ----------------
__global__ void finalize_kernel(float* __restrict__ out) {
    out[0] = -g_loss * (1.0f / (float)NN);
}

// ---------------- launch ----------------
extern "C" void kernel_launch(void* const* d_in, const int* in_sizes, int n_in,
                              void* d_out, int out_size) {
    const float* feat = (const float*)d_in[0];
    const int* lab = (const int*)d_in[1];
    float* out = (float*)d_out;

    static int smem_set = 0;
    if (!smem_set) {
        cudaFuncSetAttribute(gemm_rowsum_kernel,
                             cudaFuncAttributeMaxDynamicSharedMemorySize, GSMEM);
        cudaFuncSetAttribute(pos_gram_kernel,
                             cudaFuncAttributeMaxDynamicSharedMemorySize, CSMEM);
        smem_set = 1;
    }

    normalize_setup_kernel<<<1025, 256>>>(feat, lab);
    gemm_rowsum_kernel<<<GGRID, 256, GSMEM>>>();
    pos_gram_kernel<<<NCLS * SPLIT, 256, CSMEM>>>();
    pos_loss_kernel<<<NCLS * SPLIT, 256>>>();
    finalize_kernel<<<1, 1>>>(out);
}

// round 12
// speedup vs baseline: 1.0773x; 1.0539x over previous
#include <cuda_runtime.h>
#include <cuda_bf16.h>
#include <cstdint>

#define BN    4096
#define NV    2
#define DD    128
#define NN    8192
#define NCLS  100
#define TILE  128
#define NT    (NN/TILE)            // 64
#define NTILES (NT*(NT+1)/2)       // 2080
#define INV_T 14.285714285714286f
#define EXPC  20.60992915555662f   // INV_T * log2(e)
#define LN2   0.6931471805599453f
#define GGRID 296                  // one full wave (148 SMs x 2 CTA)
#define GSMEM (98304)              // A(32K) + B0(32K) + B1(32K)
#define MAXN  192
#define SPLIT 8
#define CSMEM (MAXN * 65 * 4)

// ---------------- device scratch ----------------
__device__ __align__(16) __nv_bfloat16  g_Qh[(size_t)NN * DD];
__device__ float g_allsum[NN];
__device__ float g_possum[NN];
__device__ float g_loss;
__device__ int   g_offset[NCLS + 1];
__device__ int   g_list[BN];
__device__ float g_Lmat[(size_t)NCLS * MAXN * MAXN];

// ---------------- helpers ----------------
__device__ __forceinline__ uint32_t smem_u32(const void* p) {
    uint32_t a;
    asm("{ .reg .u64 t; cvta.to.shared.u64 t, %1; cvt.u32.u64 %0, t; }" : "=r"(a) : "l"(p));
    return a;
}
__device__ __forceinline__ void ldsm_x4(uint32_t* r, uint32_t addr) {
    asm volatile("ldmatrix.sync.aligned.m8n8.x4.shared.b16 {%0,%1,%2,%3}, [%4];"
                 : "=r"(r[0]), "=r"(r[1]), "=r"(r[2]), "=r"(r[3]) : "r"(addr));
}
__device__ __forceinline__ void mma16816(float* c, const uint32_t* a, uint32_t b0, uint32_t b1) {
    asm volatile(
        "mma.sync.aligned.m16n8k16.row.col.f32.bf16.bf16.f32 "
        "{%0,%1,%2,%3}, {%4,%5,%6,%7}, {%8,%9}, {%0,%1,%2,%3};"
        : "+f"(c[0]), "+f"(c[1]), "+f"(c[2]), "+f"(c[3])
        : "r"(a[0]), "r"(a[1]), "r"(a[2]), "r"(a[3]), "r"(b0), "r"(b1));
}
__device__ __forceinline__ float ex2f(float x) {
    float y; asm("ex2.approx.f32 %0, %1;" : "=f"(y) : "f"(x)); return y;
}
__device__ __forceinline__ float lg2f(float x) {
    float y; asm("lg2.approx.f32 %0, %1;" : "=f"(y) : "f"(x)); return y;
}
__device__ __forceinline__ float exp_m(float dot) { return ex2f(dot * EXPC); }
__device__ __forceinline__ float2 bf2f(uint32_t u) {
    float2 r;
    r.x = __uint_as_float(u << 16);
    r.y = __uint_as_float(u & 0xFFFF0000u);
    return r;
}
__device__ __forceinline__ void cp16(uint32_t saddr, const void* g) {
    asm volatile("cp.async.cg.shared.global [%0], [%1], 16;" :: "r"(saddr), "l"(g));
}
__device__ __forceinline__ void cp_b_tile(uint32_t sbase, int colbase, int tid) {
#pragma unroll
    for (int i = 0; i < 8; i++) {
        int idx = tid + i * 256;
        int r = idx >> 4, cc = idx & 15;
        const uint4* g = ((const uint4*)(g_Qh + (size_t)(colbase + r) * DD)) + cc;
        cp16(sbase + (uint32_t)(r * 256 + ((cc ^ (r & 7)) << 4)), g);
    }
    asm volatile("cp.async.commit_group;" ::: "memory");
}

// ---------------- 1: normalize (blocks 0..1023) + fused setup (block 1024) ----------------
__global__ void normalize_setup_kernel(const float* __restrict__ feat,
                                       const int* __restrict__ lab) {
    if (blockIdx.x == 1024) {
        __shared__ int scount[NCLS], soff[NCLS + 1], scur[NCLS];
        int tid = threadIdx.x;
        if (tid < NCLS) { scount[tid] = 0; scur[tid] = 0; }
        __syncthreads();
        for (int t = tid; t < BN; t += 256) atomicAdd(&scount[lab[t]], 1);
        __syncthreads();
        if (tid == 0) {
            int a = 0;
            for (int c = 0; c < NCLS; c++) { soff[c] = a; a += scount[c]; }
            soff[NCLS] = a;
            g_loss = 0.f;
        }
        __syncthreads();
        for (int t = tid; t < BN; t += 256) {
            int c = lab[t];
            g_list[soff[c] + atomicAdd(&scur[c], 1)] = t;
        }
        if (tid <= NCLS) g_offset[tid] = soff[tid];
        for (int t = tid; t < NN; t += 256) g_allsum[t] = 0.f;
        return;
    }
    int warp = threadIdx.x >> 5, lane = threadIdx.x & 31;
    int row = blockIdx.x * 8 + warp;
    int v = row >> 12, b = row & (BN - 1);
    float4 x = ((const float4*)(feat + (size_t)(b * NV + v) * DD))[lane];
    float ss = x.x * x.x + x.y * x.y + x.z * x.z + x.w * x.w;
#pragma unroll
    for (int o = 16; o; o >>= 1) ss += __shfl_xor_sync(0xffffffffu, ss, o);
    float inv = rsqrtf(ss);
    uint32_t h01 = (uint32_t)__bfloat16_as_ushort(__float2bfloat16(x.x * inv)) |
                   ((uint32_t)__bfloat16_as_ushort(__float2bfloat16(x.y * inv)) << 16);
    uint32_t h23 = (uint32_t)__bfloat16_as_ushort(__float2bfloat16(x.z * inv)) |
                   ((uint32_t)__bfloat16_as_ushort(__float2bfloat16(x.w * inv)) << 16);
    ((uint2*)(g_Qh + (size_t)row * DD))[lane] = make_uint2(h01, h23);
}

// ---------------- 2: single-wave balanced GEMM (contiguous triangular ranges) ----------------
__global__ void __launch_bounds__(256, 2) gemm_rowsum_kernel() {
    extern __shared__ __align__(16) char smem[];
    uint32_t sA = smem_u32(smem);

    int bidx = blockIdx.x;
    int t  = (int)(((long long)bidx * NTILES) / GGRID);
    int t1 = (int)(((long long)(bidx + 1) * NTILES) / GGRID);

    // decode t -> (ti, tj)
    int ti = 0, rem = t;
    while (rem >= NT - ti) { rem -= NT - ti; ti++; }
    int tj = ti + rem;

    int tid = threadIdx.x;
    int w = tid >> 5, ln = tid & 31;
    int wm = w >> 2, wn = w & 3;

    int a_r = wm * 64 + (ln & 15);
    int b_r = wn * 32 + (ln & 7) + ((ln >> 4) << 3);
    int a_cs = (ln >> 4);
    int b_cs = ((ln >> 3) & 1);
    int ln7 = ln & 7;
    int r0 = ln >> 2;
    int c0 = (ln & 3) * 2;

    while (t < t1) {
        // segment: tiles of the same ti row-band, [tj, tj+seg)
        int seg = t1 - t;
        int row_rem = NT - tj;
        if (seg > row_rem) seg = row_rem;
        int rowbase = ti * TILE;

        // A tile for this band (prior segment's reads fenced by trailing sync)
#pragma unroll
        for (int i = 0; i < 8; i++) {
            int idx = tid + i * 256;
            int r = idx >> 4, cc = idx & 15;
            uint4 va = *((const uint4*)(g_Qh + (size_t)(rowbase + r) * DD) + cc);
            *(uint4*)(smem + r * 256 + ((cc ^ (r & 7)) << 4)) = va;
        }
        cp_b_tile(sA + 32768u, tj * TILE, tid);

        float rsacc[4][2];
#pragma unroll
        for (int q = 0; q < 4; q++) { rsacc[q][0] = 0.f; rsacc[q][1] = 0.f; }

        for (int s = 0; s < seg; s++) {
            int tjc = tj + s;
            uint32_t sB = sA + 32768u + ((uint32_t)(s & 1) << 15);
            bool diag = (ti == tjc);
            int colbase = tjc * TILE;

            if (s + 1 < seg) {
                cp_b_tile(sA + 32768u + ((uint32_t)((s + 1) & 1) << 15), (tjc + 1) * TILE, tid);
                asm volatile("cp.async.wait_group 1;" ::: "memory");
            } else {
                asm volatile("cp.async.wait_group 0;" ::: "memory");
            }
            __syncthreads();

            float acc[4][4][4];
#pragma unroll
            for (int mt = 0; mt < 4; mt++)
#pragma unroll
                for (int nj = 0; nj < 4; nj++)
#pragma unroll
                    for (int q = 0; q < 4; q++) acc[mt][nj][q] = 0.f;

#pragma unroll
            for (int ks = 0; ks < 8; ks++) {
                uint32_t a[4][4], b[2][4];
#pragma unroll
                for (int mt = 0; mt < 4; mt++) {
                    int r = a_r + mt * 16;
                    ldsm_x4(a[mt], sA + (uint32_t)(r * 256 + (((ks * 2 + a_cs) ^ ln7) << 4)));
                }
#pragma unroll
                for (int ng = 0; ng < 2; ng++) {
                    int r = b_r + ng * 16;
                    ldsm_x4(b[ng], sB + (uint32_t)(r * 256 + (((ks * 2 + b_cs) ^ ln7) << 4)));
                }
#pragma unroll
                for (int mt = 0; mt < 4; mt++)
#pragma unroll
                    for (int nj = 0; nj < 4; nj++)
                        mma16816(acc[mt][nj], a[mt], b[nj >> 1][(nj & 1) * 2], b[nj >> 1][(nj & 1) * 2 + 1]);
            }

            float cs[4][2];
#pragma unroll
            for (int q = 0; q < 4; q++) { cs[q][0] = 0.f; cs[q][1] = 0.f; }
#pragma unroll
            for (int mt = 0; mt < 4; mt++) {
                int rg0 = wm * 64 + mt * 16 + r0, rg1 = rg0 + 8;
#pragma unroll
                for (int nj = 0; nj < 4; nj++) {
                    int cg0 = wn * 32 + nj * 8 + c0;
                    float e0 = exp_m(acc[mt][nj][0]);
                    float e1 = exp_m(acc[mt][nj][1]);
                    float e2 = exp_m(acc[mt][nj][2]);
                    float e3 = exp_m(acc[mt][nj][3]);
                    if (diag) {
                        if (rg0 == cg0)     e0 = 0.f;
                        if (rg0 == cg0 + 1) e1 = 0.f;
                        if (rg1 == cg0)     e2 = 0.f;
                        if (rg1 == cg0 + 1) e3 = 0.f;
                    }
                    rsacc[mt][0] += e0 + e1;  rsacc[mt][1] += e2 + e3;
                    cs[nj][0] += e0 + e2;     cs[nj][1] += e1 + e3;
                }
            }
            if (!diag) {
#pragma unroll
                for (int nj = 0; nj < 4; nj++)
#pragma unroll
                    for (int p = 0; p < 2; p++) {
                        float v = cs[nj][p];
                        v += __shfl_xor_sync(0xffffffffu, v, 4);
                        v += __shfl_xor_sync(0xffffffffu, v, 8);
                        v += __shfl_xor_sync(0xffffffffu, v, 16);
                        cs[nj][p] = v;
                    }
                if (ln < 4) {
#pragma unroll
                    for (int nj = 0; nj < 4; nj++)
#pragma unroll
                        for (int p = 0; p < 2; p++)
                            atomicAdd(&g_allsum[colbase + wn * 32 + nj * 8 + c0 + p], cs[nj][p]);
                }
            }
            __syncthreads();   // B/A reads done before next prefetch / A reload
        }

        // flush row sums for this band segment
#pragma unroll
        for (int mt = 0; mt < 4; mt++)
#pragma unroll
            for (int h = 0; h < 2; h++) {
                float v = rsacc[mt][h];
                v += __shfl_xor_sync(0xffffffffu, v, 1);
                v += __shfl_xor_sync(0xffffffffu, v, 2);
                rsacc[mt][h] = v;
            }
        if ((ln & 3) == 0) {
#pragma unroll
            for (int mt = 0; mt < 4; mt++)
#pragma unroll
                for (int h = 0; h < 2; h++)
                    atomicAdd(&g_allsum[rowbase + wm * 64 + mt * 16 + r0 + h * 8], rsacc[mt][h]);
        }

        t += seg;
        tj += seg;
        if (tj == NT) { ti++; tj = ti; }
    }
}

// ---------------- 3: per-class Gram stripes -> Lmat + possum ----------------
__global__ void __launch_bounds__(256, 2) pos_gram_kernel() {
    extern __shared__ __align__(16) uint32_t Cs[];   // [MAXN][65]
    __shared__ int jmap[MAXN];
    int c = blockIdx.x >> 3, stripe = blockIdx.x & 7;
    int start = g_offset[c];
    int n = 2 * (g_offset[c + 1] - start);
    if (n > MAXN) n = MAXN;
    int tid = threadIdx.x, w = tid >> 5, ln = tid & 31;
    float* Lc = g_Lmat + (size_t)c * MAXN * MAXN;

    for (int idx = tid; idx < n * 32; idx += 256) {
        int r = idx >> 5, kk = idx & 31;
        int j = ((r & 1) << 12) + g_list[start + (r >> 1)];
        uint2 v = ((const uint2*)g_Qh)[(size_t)j * 32 + kk];
        Cs[r * 65 + kk * 2] = v.x;
        Cs[r * 65 + kk * 2 + 1] = v.y;
        if (kk == 0) jmap[r] = j;
    }
    __syncthreads();

    for (int k = w;; k += 8) {
        int p = stripe + SPLIT * k;
        if (p >= n) break;
        const uint32_t* Cp = Cs + p * 65;
        float* Lp = Lc + p * MAXN;
        float rsum = 0.f;
        for (int qb = 0; qb < n; qb += 32) {
            int q = qb + ln;
            bool qok = (q < n);
            const uint32_t* Cq = Cs + (qok ? q : 0) * 65;
            float a0 = 0.f, a1 = 0.f, a2 = 0.f, a3 = 0.f;
#pragma unroll 4
            for (int kp = 0; kp < 64; kp += 4) {
                float2 q0 = bf2f(Cq[kp]),     p0 = bf2f(Cp[kp]);
                float2 q1 = bf2f(Cq[kp + 1]), p1 = bf2f(Cp[kp + 1]);
                float2 q2 = bf2f(Cq[kp + 2]), p2 = bf2f(Cp[kp + 2]);
                float2 q3 = bf2f(Cq[kp + 3]), p3 = bf2f(Cp[kp + 3]);
                a0 = fmaf(p0.x, q0.x, a0); a0 = fmaf(p0.y, q0.y, a0);
                a1 = fmaf(p1.x, q1.x, a1); a1 = fmaf(p1.y, q1.y, a1);
                a2 = fmaf(p2.x, q2.x, a2); a2 = fmaf(p2.y, q2.y, a2);
                a3 = fmaf(p3.x, q3.x, a3); a3 = fmaf(p3.y, q3.y, a3);
            }
            float acc = (a0 + a1) + (a2 + a3);
            if (qok) {
                Lp[q] = acc;
                if (q != p) rsum += exp_m(acc);
            }
        }
#pragma unroll
        for (int o = 16; o; o >>= 1) rsum += __shfl_xor_sync(0xffffffffu, rsum, o);
        if (ln == 0) g_possum[jmap[p]] = rsum;
    }
}

// ---------------- 4: loss from Lmat + negsum ----------------
__global__ void __launch_bounds__(256) pos_loss_kernel() {
    __shared__ float ns[MAXN];
    __shared__ float wl[8];
    int c = blockIdx.x >> 3, stripe = blockIdx.x & 7;
    int start = g_offset[c];
    int n = 2 * (g_offset[c + 1] - start);
    if (n > MAXN) n = MAXN;
    int tid = threadIdx.x, w = tid >> 5, ln = tid & 31;
    const float* Lc = g_Lmat + (size_t)c * MAXN * MAXN;

    for (int r = tid; r < n; r += 256) {
        int j = ((r & 1) << 12) + g_list[start + (r >> 1)];
        ns[r] = g_allsum[j] - g_possum[j];
    }
    __syncthreads();

    float part = 0.f;
    for (int k = w;; k += 8) {
        int p = stripe + SPLIT * k;
        if (p >= n) break;
        const float* Lp = Lc + p * MAXN;
        for (int qb = 0; qb < n; qb += 32) {
            int q = qb + ln;
            if (q < n && q != p) {
                float dot = Lp[q];
                float e = exp_m(dot);
                part += dot * INV_T - LN2 * lg2f(ns[q] + e);
            }
        }
    }
#pragma unroll
    for (int o = 16; o; o >>= 1) part += __shfl_xor_sync(0xffffffffu, part, o);
    if (ln == 0) wl[w] = part;
    __syncthreads();
    if (tid == 0) {
        float s = 0.f;
#pragma unroll
        for (int i = 0; i < 8; i++) s += wl[i];
        atomicAdd(&g_loss, s);
    }
}

// ---------------- 5: finalize ----------------
__global__ void finalize_kernel(float* __restrict__ out) {
    out[0] = -g_loss * (1.0f / (float)NN);
}

// ---------------- launch ----------------
extern "C" void kernel_launch(void* const* d_in, const int* in_sizes, int n_in,
                              void* d_out, int out_size) {
    const float* feat = (const float*)d_in[0];
    const int* lab = (const int*)d_in[1];
    float* out = (float*)d_out;

    static int smem_set = 0;
    if (!smem_set) {
        cudaFuncSetAttribute(gemm_rowsum_kernel,
                             cudaFuncAttributeMaxDynamicSharedMemorySize, GSMEM);
        cudaFuncSetAttribute(pos_gram_kernel,
                             cudaFuncAttributeMaxDynamicSharedMemorySize, CSMEM);
        smem_set = 1;
    }

    normalize_setup_kernel<<<1025, 256>>>(feat, lab);
    gemm_rowsum_kernel<<<GGRID, 256, GSMEM>>>();
    pos_gram_kernel<<<NCLS * SPLIT, 256, CSMEM>>>();
    pos_loss_kernel<<<NCLS * SPLIT, 256>>>();
    finalize_kernel<<<1, 1>>>(out);
}

// round 14
// speedup vs baseline: 1.0836x; 1.0058x over previous
#include <cuda_runtime.h>
#include <cuda_bf16.h>
#include <cstdint>

#define BN    4096
#define NV    2
#define DD    128
#define NN    8192
#define NCLS  100
#define TILE  128
#define NT    (NN/TILE)            // 64
#define NTILES (NT*(NT+1)/2)       // 2080
#define INV_T 14.285714285714286f
#define EXPC  20.60992915555662f   // INV_T * log2(e)
#define LN2   0.6931471805599453f
#define GGRID 296                  // one full wave (148 SMs x 2 CTA)
#define GSMEM (98304)              // A(32K) + B0(32K) + B1(32K); pos tail reuses it
#define MAXN  192
#define SPLIT 8
#define NPOS  (NCLS * SPLIT)       // 800 pos-gram tasks

// ---------------- device scratch ----------------
__device__ __align__(16) __nv_bfloat16  g_Qh[(size_t)NN * DD];
__device__ float g_allsum[NN];
__device__ float g_possum[NN];
__device__ float g_loss;
__device__ int   g_offset[NCLS + 1];
__device__ int   g_list[BN];
__device__ float g_Lmat[(size_t)NCLS * MAXN * MAXN];

// ---------------- helpers ----------------
__device__ __forceinline__ uint32_t smem_u32(const void* p) {
    uint32_t a;
    asm("{ .reg .u64 t; cvta.to.shared.u64 t, %1; cvt.u32.u64 %0, t; }" : "=r"(a) : "l"(p));
    return a;
}
__device__ __forceinline__ void ldsm_x4(uint32_t* r, uint32_t addr) {
    asm volatile("ldmatrix.sync.aligned.m8n8.x4.shared.b16 {%0,%1,%2,%3}, [%4];"
                 : "=r"(r[0]), "=r"(r[1]), "=r"(r[2]), "=r"(r[3]) : "r"(addr));
}
__device__ __forceinline__ void mma16816(float* c, const uint32_t* a, uint32_t b0, uint32_t b1) {
    asm volatile(
        "mma.sync.aligned.m16n8k16.row.col.f32.bf16.bf16.f32 "
        "{%0,%1,%2,%3}, {%4,%5,%6,%7}, {%8,%9}, {%0,%1,%2,%3};"
        : "+f"(c[0]), "+f"(c[1]), "+f"(c[2]), "+f"(c[3])
        : "r"(a[0]), "r"(a[1]), "r"(a[2]), "r"(a[3]), "r"(b0), "r"(b1));
}
__device__ __forceinline__ float ex2f(float x) {
    float y; asm("ex2.approx.f32 %0, %1;" : "=f"(y) : "f"(x)); return y;
}
__device__ __forceinline__ float lg2f(float x) {
    float y; asm("lg2.approx.f32 %0, %1;" : "=f"(y) : "f"(x)); return y;
}
__device__ __forceinline__ float exp_m(float dot) { return ex2f(dot * EXPC); }
__device__ __forceinline__ float2 bf2f(uint32_t u) {
    float2 r;
    r.x = __uint_as_float(u << 16);
    r.y = __uint_as_float(u & 0xFFFF0000u);
    return r;
}
__device__ __forceinline__ void cp16(uint32_t saddr, const void* g) {
    asm volatile("cp.async.cg.shared.global [%0], [%1], 16;" :: "r"(saddr), "l"(g));
}
__device__ __forceinline__ void cp_b_tile(uint32_t sbase, int colbase, int tid) {
#pragma unroll
    for (int i = 0; i < 8; i++) {
        int idx = tid + i * 256;
        int r = idx >> 4, cc = idx & 15;
        const uint4* g = ((const uint4*)(g_Qh + (size_t)(colbase + r) * DD)) + cc;
        cp16(sbase + (uint32_t)(r * 256 + ((cc ^ (r & 7)) << 4)), g);
    }
    asm volatile("cp.async.commit_group;" ::: "memory");
}

// ---------------- 1: normalize (blocks 0..1023) + fused setup (block 1024) ----------------
__global__ void normalize_setup_kernel(const float* __restrict__ feat,
                                       const int* __restrict__ lab) {
    if (blockIdx.x == 1024) {
        __shared__ int scount[NCLS], soff[NCLS + 1], scur[NCLS];
        int tid = threadIdx.x;
        if (tid < NCLS) { scount[tid] = 0; scur[tid] = 0; }
        __syncthreads();
        for (int t = tid; t < BN; t += 256) atomicAdd(&scount[lab[t]], 1);
        __syncthreads();
        if (tid == 0) {
            int a = 0;
            for (int c = 0; c < NCLS; c++) { soff[c] = a; a += scount[c]; }
            soff[NCLS] = a;
            g_loss = 0.f;
        }
        __syncthreads();
        for (int t = tid; t < BN; t += 256) {
            int c = lab[t];
            g_list[soff[c] + atomicAdd(&scur[c], 1)] = t;
        }
        if (tid <= NCLS) g_offset[tid] = soff[tid];
        for (int t = tid; t < NN; t += 256) g_allsum[t] = 0.f;
        return;
    }
    int warp = threadIdx.x >> 5, lane = threadIdx.x & 31;
    int row = blockIdx.x * 8 + warp;
    int v = row >> 12, b = row & (BN - 1);
    float4 x = ((const float4*)(feat + (size_t)(b * NV + v) * DD))[lane];
    float ss = x.x * x.x + x.y * x.y + x.z * x.z + x.w * x.w;
#pragma unroll
    for (int o = 16; o; o >>= 1) ss += __shfl_xor_sync(0xffffffffu, ss, o);
    float inv = rsqrtf(ss);
    uint32_t h01 = (uint32_t)__bfloat16_as_ushort(__float2bfloat16(x.x * inv)) |
                   ((uint32_t)__bfloat16_as_ushort(__float2bfloat16(x.y * inv)) << 16);
    uint32_t h23 = (uint32_t)__bfloat16_as_ushort(__float2bfloat16(x.z * inv)) |
                   ((uint32_t)__bfloat16_as_ushort(__float2bfloat16(x.w * inv)) << 16);
    ((uint2*)(g_Qh + (size_t)row * DD))[lane] = make_uint2(h01, h23);
}

// ---------------- pos-gram task (runs in gemm tail, smem reused) ----------------
__device__ __forceinline__ void pos_gram_task(uint32_t* Cs, int* jmap, int task,
                                              int tid, int w, int ln) {
    int c = task >> 3, stripe = task & 7;
    int start = g_offset[c];
    int n = 2 * (g_offset[c + 1] - start);
    if (n > MAXN) n = MAXN;
    float* Lc = g_Lmat + (size_t)c * MAXN * MAXN;

    for (int idx = tid; idx < n * 32; idx += 256) {
        int r = idx >> 5, kk = idx & 31;
        int j = ((r & 1) << 12) + g_list[start + (r >> 1)];
        uint2 v = ((const uint2*)g_Qh)[(size_t)j * 32 + kk];
        Cs[r * 65 + kk * 2] = v.x;
        Cs[r * 65 + kk * 2 + 1] = v.y;
        if (kk == 0) jmap[r] = j;
    }
    __syncthreads();

    for (int k = w;; k += 8) {
        int p = stripe + SPLIT * k;
        if (p >= n) break;
        const uint32_t* Cp = Cs + p * 65;
        float* Lp = Lc + p * MAXN;
        float rsum = 0.f;
        for (int qb = 0; qb < n; qb += 32) {
            int q = qb + ln;
            bool qok = (q < n);
            const uint32_t* Cq = Cs + (qok ? q : 0) * 65;
            float a0 = 0.f, a1 = 0.f, a2 = 0.f, a3 = 0.f;
#pragma unroll 4
        for (int kp = 0; kp < 64; kp += 4) {
                float2 q0 = bf2f(Cq[kp]),     p0 = bf2f(Cp[kp]);
                float2 q1 = bf2f(Cq[kp + 1]), p1 = bf2f(Cp[kp + 1]);
                float2 q2 = bf2f(Cq[kp + 2]), p2 = bf2f(Cp[kp + 2]);
                float2 q3 = bf2f(Cq[kp + 3]), p3 = bf2f(Cp[kp + 3]);
                a0 = fmaf(p0.x, q0.x, a0); a0 = fmaf(p0.y, q0.y, a0);
                a1 = fmaf(p1.x, q1.x, a1); a1 = fmaf(p1.y, q1.y, a1);
                a2 = fmaf(p2.x, q2.x, a2); a2 = fmaf(p2.y, q2.y, a2);
                a3 = fmaf(p3.x, q3.x, a3); a3 = fmaf(p3.y, q3.y, a3);
            }
            float acc = (a0 + a1) + (a2 + a3);
            if (qok) {
                Lp[q] = acc;
                if (q != p) rsum += exp_m(acc);
            }
        }
#pragma unroll
        for (int o = 16; o; o >>= 1) rsum += __shfl_xor_sync(0xffffffffu, rsum, o);
        if (ln == 0) g_possum[jmap[p]] = rsum;
    }
}

// ---------------- 2: single-wave GEMM + fused pos-gram tail ----------------
__global__ void __launch_bounds__(256, 2) gemm_rowsum_kernel() {
    extern __shared__ __align__(16) char smem[];
    __shared__ int jmap[MAXN];
    uint32_t sA = smem_u32(smem);

    int bidx = blockIdx.x;
    int t  = (int)(((long long)bidx * NTILES) / GGRID);
    int t1 = (int)(((long long)(bidx + 1) * NTILES) / GGRID);

    int ti = 0, rem = t;
    while (rem >= NT - ti) { rem -= NT - ti; ti++; }
    int tj = ti + rem;

    int tid = threadIdx.x;
    int w = tid >> 5, ln = tid & 31;
    int wm = w >> 2, wn = w & 3;

    int a_r = wm * 64 + (ln & 15);
    int b_r = wn * 32 + (ln & 7) + ((ln >> 4) << 3);
    int a_cs = (ln >> 4);
    int b_cs = ((ln >> 3) & 1);
    int ln7 = ln & 7;
    int r0 = ln >> 2;
    int c0 = (ln & 3) * 2;

    bool first_band = true;
    while (t < t1) {
        int seg = t1 - t;
        int row_rem = NT - tj;
        if (seg > row_rem) seg = row_rem;
        int rowbase = ti * TILE;

        if (!first_band) __syncthreads();   // prior band's A/B reads done
        first_band = false;

        // A tile for this band
#pragma unroll
        for (int i = 0; i < 8; i++) {
            int idx = tid + i * 256;
            int r = idx >> 4, cc = idx & 15;
            uint4 va = *((const uint4*)(g_Qh + (size_t)(rowbase + r) * DD) + cc);
            *(uint4*)(smem + r * 256 + ((cc ^ (r & 7)) << 4)) = va;
        }
        cp_b_tile(sA + 32768u, tj * TILE, tid);

        float rsacc[4][2];
#pragma unroll
        for (int q = 0; q < 4; q++) { rsacc[q][0] = 0.f; rsacc[q][1] = 0.f; }

        for (int s = 0; s < seg; s++) {
            int tjc = tj + s;
            uint32_t sB = sA + 32768u + ((uint32_t)(s & 1) << 15);
            bool diag = (ti == tjc);
            int colbase = tjc * TILE;

            asm volatile("cp.async.wait_group 0;" ::: "memory");
            __syncthreads();   // B_s visible; all warps done reading B_{s-1}
            if (s + 1 < seg)
                cp_b_tile(sA + 32768u + ((uint32_t)((s + 1) & 1) << 15), (tjc + 1) * TILE, tid);

            float acc[4][4][4];
#pragma unroll
            for (int mt = 0; mt < 4; mt++)
#pragma unroll
                for (int nj = 0; nj < 4; nj++)
#pragma unroll
                    for (int q = 0; q < 4; q++) acc[mt][nj][q] = 0.f;

#pragma unroll
            for (int ks = 0; ks < 8; ks++) {
                uint32_t a[4][4], b[2][4];
#pragma unroll
                for (int mt = 0; mt < 4; mt++) {
                    int r = a_r + mt * 16;
                    ldsm_x4(a[mt], sA + (uint32_t)(r * 256 + (((ks * 2 + a_cs) ^ ln7) << 4)));
                }
#pragma unroll
                for (int ng = 0; ng < 2; ng++) {
                    int r = b_r + ng * 16;
                    ldsm_x4(b[ng], sB + (uint32_t)(r * 256 + (((ks * 2 + b_cs) ^ ln7) << 4)));
                }
#pragma unroll
                for (int mt = 0; mt < 4; mt++)
#pragma unroll
                    for (int nj = 0; nj < 4; nj++)
                        mma16816(acc[mt][nj], a[mt], b[nj >> 1][(nj & 1) * 2], b[nj >> 1][(nj & 1) * 2 + 1]);
            }

            float cs[4][2];
#pragma unroll
            for (int q = 0; q < 4; q++) { cs[q][0] = 0.f; cs[q][1] = 0.f; }
#pragma unroll
            for (int mt = 0; mt < 4; mt++) {
                int rg0 = wm * 64 + mt * 16 + r0, rg1 = rg0 + 8;
#pragma unroll
                for (int nj = 0; nj < 4; nj++) {
                    int cg0 = wn * 32 + nj * 8 + c0;
                    float e0 = exp_m(acc[mt][nj][0]);
                    float e1 = exp_m(acc[mt][nj][1]);
                    float e2 = exp_m(acc[mt][nj][2]);
                    float e3 = exp_m(acc[mt][nj][3]);
                    if (diag) {
                        if (rg0 == cg0)     e0 = 0.f;
                        if (rg0 == cg0 + 1) e1 = 0.f;
                        if (rg1 == cg0)     e2 = 0.f;
                        if (rg1 == cg0 + 1) e3 = 0.f;
                    }
                    rsacc[mt][0] += e0 + e1;  rsacc[mt][1] += e2 + e3;
                    cs[nj][0] += e0 + e2;     cs[nj][1] += e1 + e3;
                }
            }
            if (!diag) {
#pragma unroll
                for (int nj = 0; nj < 4; nj++)
#pragma unroll
                    for (int p = 0; p < 2; p++) {
                        float v = cs[nj][p];
                        v += __shfl_xor_sync(0xffffffffu, v, 4);
                        v += __shfl_xor_sync(0xffffffffu, v, 8);
                        v += __shfl_xor_sync(0xffffffffu, v, 16);
                        cs[nj][p] = v;
                    }
                if (ln < 4) {
#pragma unroll
                    for (int nj = 0; nj < 4; nj++)
#pragma unroll
                        for (int p = 0; p < 2; p++)
                            atomicAdd(&g_allsum[colbase + wn * 32 + nj * 8 + c0 + p], cs[nj][p]);
                }
            }
        }

        // flush row sums for this band segment
#pragma unroll
        for (int mt = 0; mt < 4; mt++)
#pragma unroll
            for (int h = 0; h < 2; h++) {
                float v = rsacc[mt][h];
                v += __shfl_xor_sync(0xffffffffu, v, 1);
                v += __shfl_xor_sync(0xffffffffu, v, 2);
                rsacc[mt][h] = v;
            }
        if ((ln & 3) == 0) {
#pragma unroll
            for (int mt = 0; mt < 4; mt++)
#pragma unroll
                for (int h = 0; h < 2; h++)
                    atomicAdd(&g_allsum[rowbase + wm * 64 + mt * 16 + r0 + h * 8], rsacc[mt][h]);
        }

        t += seg;
        tj += seg;
        if (tj == NT) { ti++; tj = ti; }
    }

    // ---- fused pos-gram tail: grid-stride over the 800 class-stripe tasks ----
    uint32_t* Cs = (uint32_t*)smem;   // 192*65*4 = 49920 B <= 96 KB
    for (int task = bidx; task < NPOS; task += GGRID) {
        __syncthreads();   // gemm smem reads / prior task done before overwrite
        pos_gram_task(Cs, jmap, task, tid, w, ln);
    }
}

// ---------------- 3: loss from Lmat + negsum ----------------
__global__ void __launch_bounds__(256) pos_loss_kernel() {
    __shared__ float ns[MAXN];
    __shared__ float wl[8];
    int c = blockIdx.x >> 3, stripe = blockIdx.x & 7;
    int start = g_offset[c];
    int n = 2 * (g_offset[c + 1] - start);
    if (n > MAXN) n = MAXN;
    int tid = threadIdx.x, w = tid >> 5, ln = tid & 31;
    const float* Lc = g_Lmat + (size_t)c * MAXN * MAXN;

    for (int r = tid; r < n; r += 256) {
        int j = ((r & 1) << 12) + g_list[start + (r >> 1)];
        ns[r] = g_allsum[j] - g_possum[j];
    }
    __syncthreads();

    float part = 0.f;
    for (int k = w;; k += 8) {
        int p = stripe + SPLIT * k;
        if (p >= n) break;
        const float* Lp = Lc + p * MAXN;
        for (int qb = 0; qb < n; qb += 32) {
            int q = qb + ln;
            if (q < n && q != p) {
                float dot = Lp[q];
                float e = exp_m(dot);
                part += dot * INV_T - LN2 * lg2f(ns[q] + e);
            }
        }
    }
#pragma unroll
    for (int o = 16; o; o >>= 1) part += __shfl_xor_sync(0xffffffffu, part, o);
    if (ln == 0) wl[w] = part;
    __syncthreads();
    if (tid == 0) {
        float s = 0.f;
#pragma unroll
        for (int i = 0; i < 8; i++) s += wl[i];
        atomicAdd(&g_loss, s);
    }
}

// ---------------- 4: finalize ----------------
__global__ void finalize_kernel(float* __restrict__ out) {
    out[0] = -g_loss * (1.0f / (float)NN);
}

// ---------------- launch ----------------
extern "C" void kernel_launch(void* const* d_in, const int* in_sizes, int n_in,
                              void* d_out, int out_size) {
    const float* feat = (const float*)d_in[0];
    const int* lab = (const int*)d_in[1];
    float* out = (float*)d_out;

    static int smem_set = 0;
    if (!smem_set) {
        cudaFuncSetAttribute(gemm_rowsum_kernel,
                             cudaFuncAttributeMaxDynamicSharedMemorySize, GSMEM);
        smem_set = 1;
    }

    normalize_setup_kernel<<<1025, 256>>>(feat, lab);
    gemm_rowsum_kernel<<<GGRID, 256, GSMEM>>>();
    pos_loss_kernel<<<NPOS, 256>>>();
    finalize_kernel<<<1, 1>>>(out);
}